// round 12
// baseline (speedup 1.0000x reference)
#include <cuda_runtime.h>
#include <cuda_bf16.h>

// ---------------- problem constants ----------------
#define H_IMG   2048
#define W_IMG   2048
#define C_IMG   3
#define RAD     5
#define NITER   10
#define PH      (H_IMG + 2*RAD)   // 2058
#define PW      (W_IMG + 2*RAD)   // 2058

// Guarded buffer layout: interior pixel (y,x) lives at row y+GY, col x+GX.
// Guard bands stay zero so mid iterations load float4 with NO bounds checks.
#define GY      8
#define GX      8
#define PROWS   2104
#define PITCH   2208
#define PLANE   (PROWS * PITCH)
#define BUFSZ   (C_IMG * PLANE)

__device__ float g_U[2][BUFSZ];

// ---------------- zero all guard bands of both buffers ----------------
#define NA (8 * PITCH)
#define NB (38 * PITCH)
#define NL (PH * 8)
#define NR (PH * 142)
#define NGUARD (NA + NB + NL + NR)

__global__ void swf_guard_zero() {
    int plane = blockIdx.y;            // 0..5 : b*3 + c
    int b = plane / 3;
    int c = plane - b * 3;
    float* base = g_U[b] + c * PLANE;
    for (int i = blockIdx.x * blockDim.x + threadIdx.x; i < NGUARD;
         i += gridDim.x * blockDim.x) {
        int row, col, r = i;
        if (r < NA)                { row = r / PITCH;            col = r % PITCH; }
        else if ((r -= NA) < NB)   { row = 2066 + r / PITCH;     col = r % PITCH; }
        else if ((r -= NB) < NL)   { row = GY + r / 8;           col = r % 8; }
        else        { r -= NL;       row = GY + r / 142;          col = 2066 + r % 142; }
        base[row * PITCH + col] = 0.0f;
    }
}

// ---------------- one side-window iteration (3 modes) ----------------
#define TH 28
#define TROWS (TH + 2*RAD)        // 38
#define TW 128
#define TCOLS 148                 // 37 float4; bank-friendly stride
#define TC4   (TCOLS/4)           // 37
#define NF4   (TROWS * TC4)       // 1406
#define H6W   138                 // 6 segments x 23 cols, fully covered

#define MODE_FIRST 0
#define MODE_MID   1
#define MODE_LAST  2

// Stage-3 vertical walk with lead sums.
// Rings are 6-deep (subtract value read from slot j%6 BEFORE overwrite = row j-6).
// Histories are 5-deep delay lines (read slot j%5 before write = value at j-5).
// FULL=true: every row stores (only xok checked). Otherwise rows [lo,hi) store.
template<bool FULL>
__device__ __forceinline__ void walk(const float* __restrict__ hp,
                                     const float* __restrict__ hp5,
                                     const float* __restrict__ cp,
                                     float* __restrict__ ptr, int stride,
                                     int base, bool xok, int lo, int hi)
{
    const float i36 = 1.0f / 36.0f;
    const float i66 = 1.0f / 66.0f;

    float rHL[6], rHR[6], rCc[6];
    #pragma unroll
    for (int j = 0; j < 6; j++) {
        int row = base + j;
        rHL[j] = hp[row * H6W];
        rHR[j] = hp5[row * H6W];
        rCc[j] = cp[row * TCOLS];
    }

    // lead sums at j=5 (rows base+0 .. base+5)
    float A  = rHL[0] + rHL[1] + rHL[2] + rHL[3] + rHL[4] + rHL[5];
    float B  = rHR[0] + rHR[1] + rHR[2] + rHR[3] + rHR[4] + rHR[5];
    float C6 = rCc[0] + rCc[1] + rCc[2] + rCc[3] + rCc[4] + rCc[5];
    float Dw = A + B - C6;

    float Ah[5], Bh[5], Dh[5];
    Ah[0] = A; Bh[0] = B; Dh[0] = Dw;        // slot 5%5=0 holds step j=5

    // prologue j=6..9: load new row, slide windows, record history
    #pragma unroll
    for (int j = 6; j <= 9; j++) {
        int row = base + j;
        float nHL = hp[row * H6W];
        float nHR = hp5[row * H6W];
        float nCc = cp[row * TCOLS];
        A  += nHL - rHL[j % 6];              // slot holds row j-6
        B  += nHR - rHR[j % 6];
        C6 += nCc - rCc[j % 6];
        rHL[j % 6] = nHL; rHR[j % 6] = nHR; rCc[j % 6] = nCc;
        Dw = A + B - C6;
        Ah[j % 5] = A; Bh[j % 5] = B; Dh[j % 5] = Dw;
    }

    // main walk: ly = 0..TH/2-1, lead j = 10+ly
    #pragma unroll
    for (int ly = 0; ly < TH / 2; ly++) {
        const int j = 10 + ly;

        // read histories (values at j-5) BEFORE overwriting this step
        const float uL = Ah[j % 5];
        const float uR = Bh[j % 5];
        const float uF = Dh[j % 5];

        {
            int row = base + j;
            float nHL = hp[row * H6W];
            float nHR = hp5[row * H6W];
            float nCc = cp[row * TCOLS];
            A  += nHL - rHL[j % 6];
            B  += nHR - rHR[j % 6];
            C6 += nCc - rCc[j % 6];
            rHL[j % 6] = nHL; rHR[j % 6] = nHR; rCc[j % 6] = nCc;
            Dw = A + B - C6;
        }
        Ah[j % 5] = A; Bh[j % 5] = B; Dh[j % 5] = Dw;

        const float hL = rHL[(j - 5) % 6];   // row j-5 (written at j-5, not yet evicted)
        const float hR = rHR[(j - 5) % 6];
        const float c0 = rCc[(j - 5) % 6];
        const float nc0 = -c0;

        const float fL = uL + A - hL;
        const float fR = uR + B - hR;

        // deltas, reference order [LL,LR,RL,RR,L*k,R*k,k*L,k*R]
        const float d0 = fmaf(uL, i36, nc0);
        const float d1 = fmaf(uR, i36, nc0);
        const float d2 = fmaf(A,  i36, nc0);
        const float d3 = fmaf(B,  i36, nc0);
        const float d4 = fmaf(uF, i66, nc0);
        const float d5 = fmaf(Dw, i66, nc0);
        const float d6 = fmaf(fL, i66, nc0);
        const float d7 = fmaf(fR, i66, nc0);

        // Tournament argmin, first-min-on-tie; |.| free on FSETP operands.
        const float w01 = (fabsf(d1) < fabsf(d0)) ? d1 : d0;
        const float w23 = (fabsf(d3) < fabsf(d2)) ? d3 : d2;
        const float w45 = (fabsf(d5) < fabsf(d4)) ? d5 : d4;
        const float w67 = (fabsf(d7) < fabsf(d6)) ? d7 : d6;
        const float w03 = (fabsf(w23) < fabsf(w01)) ? w23 : w01;
        const float w47 = (fabsf(w67) < fabsf(w45)) ? w67 : w45;
        const float bd  = (fabsf(w47) < fabsf(w03)) ? w47 : w03;

        if (FULL) {
            if (xok) ptr[ly * stride] = c0 + bd;
        } else {
            if (xok && ly >= lo && ly < hi) ptr[ly * stride] = c0 + bd;
        }
    }
}

template<int MODE>
__global__ __launch_bounds__(256, 5)
void swf_iter(const float* __restrict__ img, float* __restrict__ out, int s) {
    float* __restrict__ Dst = (MODE == MODE_FIRST) ? g_U[0] : g_U[s ^ 1];

    __shared__ float tile[TROWS * TCOLS];   // 38*148 floats = 22.0KB
    __shared__ float h6[TROWS * H6W];       // 38*138 floats = 20.5KB

    const int c  = blockIdx.z;
    const int x0 = blockIdx.x * TW;
    const int y0 = blockIdx.y * TH;
    const int t  = threadIdx.x;             // 0..255
    float* __restrict__ Dp = Dst + c * PLANE;

    // ---- Stage 1 ----
    if (MODE == MODE_FIRST) {
        // Gather directly from HWC img with edge replicate; zero outside the
        // padded field. Scalar + clamped, paid only on iteration 0.
        for (int idx = t; idx < TROWS * TCOLS; idx += 256) {
            int r   = idx / TCOLS;
            int lxc = idx - r * TCOLS;
            int y = y0 + r - 5;             // padded-field row
            int x = x0 + lxc - 8;           // padded-field col
            float v = 0.0f;
            if (y >= 0 && y < PH && x >= 0 && x < PW) {
                int sy = y - RAD; sy = sy < 0 ? 0 : (sy > H_IMG - 1 ? H_IMG - 1 : sy);
                int sx = x - RAD; sx = sx < 0 ? 0 : (sx > W_IMG - 1 ? W_IMG - 1 : sx);
                v = img[(sy * W_IMG + sx) * C_IMG + c];
            }
            tile[idx] = v;
        }
    } else {
        // Unconditional float4 tile load (guards supply zeros).
        const float* __restrict__ Sp = g_U[s] + c * PLANE;
        const float4* __restrict__ Sp4 =
            (const float4*)(Sp + (y0 + 3) * PITCH + x0);
        float4* tile4 = (float4*)tile;
        #pragma unroll
        for (int k = 0; k < 6; k++) {
            int idx = t + k * 256;
            if (idx < NF4) {
                int r  = idx / TC4;
                int c4 = idx - r * TC4;
                tile4[r * TC4 + c4] = Sp4[r * (PITCH / 4) + c4];
            }
        }
    }
    __syncthreads();

    // ---- Stage 2: horizontal extended 6-sums, fully unrolled, LDS ring ----
    if (t < TROWS * 6) {
        int r   = t / 6;
        int seg = t - r * 6;                 // 0..5
        int sx  = seg * 23;
        const float* trow = &tile[r * TCOLS + sx];
        float* hrow = &h6[r * H6W + sx];

        float e0 = trow[3], e1 = trow[4], e2 = trow[5],
              e3 = trow[6], e4 = trow[7], e5 = trow[8];
        float sum = e0 + e1 + e2 + e3 + e4 + e5;
        hrow[0] = sum;
        float e[6] = {e0, e1, e2, e3, e4, e5};
        #pragma unroll
        for (int i = 1; i < 23; i++) {
            float nl = trow[i + 8];
            sum += nl - e[(i - 1) % 6];
            e[(i - 1) % 6] = nl;
            hrow[i] = sum;
        }
    }
    __syncthreads();

    // ---- Stage 3 ----
    const int lx   = t & 127;
    const int half = t >> 7;
    const int base = half * (TH / 2);        // 0 or 14
    const int gx   = x0 + lx;

    const float* hp  = h6 + lx;
    const float* hp5 = h6 + lx + 5;
    const float* cp  = tile + lx + 8;

    const int row0 = y0 + base;              // first output row (padded field)

    if (MODE == MODE_LAST) {
        // Write cropped HWC output directly: valid gy,gx in [5, 2052].
        const bool xok = (gx >= RAD) && (gx < PW - RAD);
        int lo = RAD - row0;        if (lo < 0) lo = 0;
        int hi = (PH - RAD) - row0; if (hi > TH / 2) hi = TH / 2;
        float* optr = out + (((row0 - RAD) * W_IMG) + (gx - RAD)) * C_IMG + c;
        walk<false>(hp, hp5, cp, optr, W_IMG * C_IMG, base, xok, lo, hi);
    } else {
        const bool xok = (gx < PW);
        float* Drow = Dp + (row0 + GY) * PITCH + gx + GX;
        if (row0 + TH / 2 <= PH) {
            walk<true>(hp, hp5, cp, Drow, PITCH, base, xok, 0, TH / 2);
        } else {
            int nvalid = PH - row0;
            walk<false>(hp, hp5, cp, Drow, PITCH, base, xok, 0, nvalid);
        }
    }
}

extern "C" void kernel_launch(void* const* d_in, const int* in_sizes, int n_in,
                              void* d_out, int out_size) {
    const float* img = (const float*)d_in[0];   // (2048,2048,3) f32; d_in[1] hardcoded
    float* out = (float*)d_out;

    {
        dim3 grid(512, 6, 1);
        swf_guard_zero<<<grid, 256>>>();
    }

    dim3 block(256, 1, 1);
    dim3 grid((PW + TW - 1) / TW, (PH + TH - 1) / TH, C_IMG);

    // iter 0: img -> g_U[0]
    swf_iter<MODE_FIRST><<<grid, block>>>(img, out, 0);
    // iters 1..8: g_U[(i-1)&1] -> g_U[i&1]
    for (int i = 1; i <= 8; i++) {
        swf_iter<MODE_MID><<<grid, block>>>(img, out, (i - 1) & 1);
    }
    // iter 9: g_U[0] -> out (cropped HWC)
    swf_iter<MODE_LAST><<<grid, block>>>(img, out, 0);
}

// round 13
// speedup vs baseline: 1.0974x; 1.0974x over previous
#include <cuda_runtime.h>
#include <cuda_bf16.h>

// ---------------- problem constants ----------------
#define H_IMG   2048
#define W_IMG   2048
#define C_IMG   3
#define RAD     5
#define NITER   10
#define PH      (H_IMG + 2*RAD)   // 2058
#define PW      (W_IMG + 2*RAD)   // 2058

// Guarded buffer layout: interior pixel (y,x) lives at row y+GY, col x+GX.
// Guard bands are NEVER written by any kernel (all stores are interior-only),
// and __device__ globals are zero-initialized at module load -> guards are
// permanently zero. Mid iterations therefore load float4 with NO bounds checks.
#define GY      8
#define GX      8
#define PROWS   2104
#define PITCH   2208
#define PLANE   (PROWS * PITCH)
#define BUFSZ   (C_IMG * PLANE)

__device__ float g_U[2][BUFSZ];

// ---------------- one side-window iteration (3 modes) ----------------
#define TH 30
#define TROWS (TH + 2*RAD)        // 40
#define TW 128
#define TCOLS 148                 // 37 float4; bank-friendly stride
#define TC4   (TCOLS/4)           // 37
#define NF4   (TROWS * TC4)       // 1480
#define H6W   138                 // 6 segments x 23 cols, fully covered

#define MODE_FIRST 0
#define MODE_MID   1
#define MODE_LAST  2

// Stage-3 vertical walk with lead sums.
// FULL=true: every row stores (only xok checked). Otherwise rows [lo,hi) store.
template<bool FULL>
__device__ __forceinline__ void walk(const float* __restrict__ hp,
                                     const float* __restrict__ hp5,
                                     const float* __restrict__ cp,
                                     float* __restrict__ ptr, int stride,
                                     int base, bool xok, int lo, int hi)
{
    const float i36 = 1.0f / 36.0f;
    const float i66 = 1.0f / 66.0f;

    float rHL[7], rHR[7], rCc[7];
    #pragma unroll
    for (int j = 0; j < 7; j++) {
        int row = base + j;
        rHL[j] = hp[row * H6W];
        rHR[j] = hp5[row * H6W];
        rCc[j] = cp[row * TCOLS];
    }

    float A  = rHL[0] + rHL[1] + rHL[2] + rHL[3] + rHL[4] + rHL[5];
    float B  = rHR[0] + rHR[1] + rHR[2] + rHR[3] + rHR[4] + rHR[5];
    float C6 = rCc[0] + rCc[1] + rCc[2] + rCc[3] + rCc[4] + rCc[5];
    float Dw = A + B - C6;

    float Ah[6], Bh[6], Dh[6];
    Ah[5] = A; Bh[5] = B; Dh[5] = Dw;

    // prologue j=6 (row already in ring)
    A  += rHL[6] - rHL[0];
    B  += rHR[6] - rHR[0];
    C6 += rCc[6] - rCc[0];
    Dw  = A + B - C6;
    Ah[0] = A; Bh[0] = B; Dh[0] = Dw;

    // prologue j=7..9
    #pragma unroll
    for (int j = 7; j <= 9; j++) {
        int row = base + j;
        float nHL = hp[row * H6W];
        float nHR = hp5[row * H6W];
        float nCc = cp[row * TCOLS];
        A  += nHL - rHL[(j - 6) % 7];
        B  += nHR - rHR[(j - 6) % 7];
        C6 += nCc - rCc[(j - 6) % 7];
        rHL[j % 7] = nHL; rHR[j % 7] = nHR; rCc[j % 7] = nCc;
        Dw = A + B - C6;
        Ah[j % 6] = A; Bh[j % 6] = B; Dh[j % 6] = Dw;
    }

    // main walk: ly = 0..TH/2-1, lead j = 10+ly
    #pragma unroll
    for (int ly = 0; ly < TH / 2; ly++) {
        const int j = 10 + ly;
        {
            int row = base + j;
            float nHL = hp[row * H6W];
            float nHR = hp5[row * H6W];
            float nCc = cp[row * TCOLS];
            A  += nHL - rHL[(j - 6) % 7];
            B  += nHR - rHR[(j - 6) % 7];
            C6 += nCc - rCc[(j - 6) % 7];
            rHL[j % 7] = nHL; rHR[j % 7] = nHR; rCc[j % 7] = nCc;
            Dw = A + B - C6;
        }

        const float uL = Ah[(j - 5) % 6];
        const float uR = Bh[(j - 5) % 6];
        const float uF = Dh[(j - 5) % 6];
        Ah[j % 6] = A; Bh[j % 6] = B; Dh[j % 6] = Dw;

        const float hL = rHL[(j - 5) % 7];
        const float hR = rHR[(j - 5) % 7];
        const float c0 = rCc[(j - 5) % 7];
        const float nc0 = -c0;

        const float fL = uL + A - hL;
        const float fR = uR + B - hR;

        // deltas, reference order [LL,LR,RL,RR,L*k,R*k,k*L,k*R]
        const float d0 = fmaf(uL, i36, nc0);
        const float d1 = fmaf(uR, i36, nc0);
        const float d2 = fmaf(A,  i36, nc0);
        const float d3 = fmaf(B,  i36, nc0);
        const float d4 = fmaf(uF, i66, nc0);
        const float d5 = fmaf(Dw, i66, nc0);
        const float d6 = fmaf(fL, i66, nc0);
        const float d7 = fmaf(fR, i66, nc0);

        // Tournament argmin, first-min-on-tie; |.| free on FSETP operands.
        const float w01 = (fabsf(d1) < fabsf(d0)) ? d1 : d0;
        const float w23 = (fabsf(d3) < fabsf(d2)) ? d3 : d2;
        const float w45 = (fabsf(d5) < fabsf(d4)) ? d5 : d4;
        const float w67 = (fabsf(d7) < fabsf(d6)) ? d7 : d6;
        const float w03 = (fabsf(w23) < fabsf(w01)) ? w23 : w01;
        const float w47 = (fabsf(w67) < fabsf(w45)) ? w67 : w45;
        const float bd  = (fabsf(w47) < fabsf(w03)) ? w47 : w03;

        if (FULL) {
            if (xok) ptr[ly * stride] = c0 + bd;
        } else {
            if (xok && ly >= lo && ly < hi) ptr[ly * stride] = c0 + bd;
        }
    }
}

template<int MODE>
__global__ __launch_bounds__(256)
void swf_iter(const float* __restrict__ img, float* __restrict__ out, int s) {
    float* __restrict__ Dst = (MODE == MODE_FIRST) ? g_U[0] : g_U[s ^ 1];

    __shared__ float tile[TROWS * TCOLS];   // 40*148 floats
    __shared__ float h6[TROWS * H6W];       // 40*138 floats

    const int c  = blockIdx.z;
    const int x0 = blockIdx.x * TW;
    const int y0 = blockIdx.y * TH;
    const int t  = threadIdx.x;             // 0..255
    float* __restrict__ Dp = Dst + c * PLANE;

    // ---- Stage 1 ----
    if (MODE == MODE_FIRST) {
        // Gather directly from HWC img with edge replicate; zero outside the
        // padded field. Scalar + clamped, paid only on iteration 0.
        for (int idx = t; idx < TROWS * TCOLS; idx += 256) {
            int r   = idx / TCOLS;
            int lxc = idx - r * TCOLS;
            int y = y0 + r - 5;             // padded-field row
            int x = x0 + lxc - 8;           // padded-field col
            float v = 0.0f;
            if (y >= 0 && y < PH && x >= 0 && x < PW) {
                int sy = y - RAD; sy = sy < 0 ? 0 : (sy > H_IMG - 1 ? H_IMG - 1 : sy);
                int sx = x - RAD; sx = sx < 0 ? 0 : (sx > W_IMG - 1 ? W_IMG - 1 : sx);
                v = img[(sy * W_IMG + sx) * C_IMG + c];
            }
            tile[idx] = v;
        }
    } else {
        // Unconditional float4 tile load (guards supply zeros).
        // Incremental source indexing: dest index is linear (idx),
        // source advances by 6 rows + 34 f4-cols per k (carry row on wrap).
        const float* __restrict__ Sp = g_U[s] + c * PLANE;
        const float4* __restrict__ Sp4 =
            (const float4*)(Sp + (y0 + 3) * PITCH + x0);
        float4* tile4 = (float4*)tile;
        int r   = t / TC4;
        int c4  = t - r * TC4;
        int src = r * (PITCH / 4) + c4;
        int idx = t;
        #pragma unroll
        for (int k = 0; k < 6; k++) {
            if (idx < NF4) {
                tile4[idx] = Sp4[src];
            }
            idx += 256;
            c4  += 256 - 6 * TC4;            // +34
            src += 6 * (PITCH / 4) + (256 - 6 * TC4);
            if (c4 >= TC4) { c4 -= TC4; src += (PITCH / 4) - TC4; }
        }
    }
    __syncthreads();

    // ---- Stage 2: horizontal extended 6-sums, fully unrolled, LDS ring ----
    if (t < TROWS * 6) {
        int r   = t / 6;
        int seg = t - r * 6;                 // 0..5
        int sx  = seg * 23;
        const float* trow = &tile[r * TCOLS + sx];
        float* hrow = &h6[r * H6W + sx];

        float e0 = trow[3], e1 = trow[4], e2 = trow[5],
              e3 = trow[6], e4 = trow[7], e5 = trow[8];
        float sum = e0 + e1 + e2 + e3 + e4 + e5;
        hrow[0] = sum;
        float e[6] = {e0, e1, e2, e3, e4, e5};
        #pragma unroll
        for (int i = 1; i < 23; i++) {
            float nl = trow[i + 8];
            sum += nl - e[(i - 1) % 6];
            e[(i - 1) % 6] = nl;
            hrow[i] = sum;
        }
    }
    __syncthreads();

    // ---- Stage 3 ----
    const int lx   = t & 127;
    const int half = t >> 7;
    const int base = half * (TH / 2);        // 0 or 15
    const int gx   = x0 + lx;

    const float* hp  = h6 + lx;
    const float* hp5 = h6 + lx + 5;
    const float* cp  = tile + lx + 8;

    const int row0 = y0 + base;              // first output row (padded field)

    if (MODE == MODE_LAST) {
        // Write cropped HWC output directly: valid gy,gx in [5, 2052].
        const bool xok = (gx >= RAD) && (gx < PW - RAD);
        int lo = RAD - row0;        if (lo < 0) lo = 0;
        int hi = (PH - RAD) - row0; if (hi > TH / 2) hi = TH / 2;
        float* optr = out + (((row0 - RAD) * W_IMG) + (gx - RAD)) * C_IMG + c;
        walk<false>(hp, hp5, cp, optr, W_IMG * C_IMG, base, xok, lo, hi);
    } else {
        const bool xok = (gx < PW);
        float* Drow = Dp + (row0 + GY) * PITCH + gx + GX;
        if (row0 + TH / 2 <= PH) {
            walk<true>(hp, hp5, cp, Drow, PITCH, base, xok, 0, TH / 2);
        } else {
            int nvalid = PH - row0;
            walk<false>(hp, hp5, cp, Drow, PITCH, base, xok, 0, nvalid);
        }
    }
}

extern "C" void kernel_launch(void* const* d_in, const int* in_sizes, int n_in,
                              void* d_out, int out_size) {
    const float* img = (const float*)d_in[0];   // (2048,2048,3) f32; d_in[1] hardcoded
    float* out = (float*)d_out;

    dim3 block(256, 1, 1);
    dim3 grid((PW + TW - 1) / TW, (PH + TH - 1) / TH, C_IMG);

    // iter 0: img -> g_U[0]
    swf_iter<MODE_FIRST><<<grid, block>>>(img, out, 0);
    // iters 1..8: g_U[(i-1)&1] -> g_U[i&1]
    for (int i = 1; i <= 8; i++) {
        swf_iter<MODE_MID><<<grid, block>>>(img, out, (i - 1) & 1);
    }
    // iter 9: g_U[0] -> out (cropped HWC)
    swf_iter<MODE_LAST><<<grid, block>>>(img, out, 0);
}

// round 14
// speedup vs baseline: 1.1163x; 1.0173x over previous
#include <cuda_runtime.h>
#include <cuda_bf16.h>

// ---------------- problem constants ----------------
#define H_IMG   2048
#define W_IMG   2048
#define C_IMG   3
#define RAD     5
#define NITER   10
#define PH      (H_IMG + 2*RAD)   // 2058
#define PW      (W_IMG + 2*RAD)   // 2058

// Guarded buffer layout: interior pixel (y,x) lives at row y+GY, col x+GX.
// Guard bands are NEVER written by any kernel (all stores are interior-only),
// and __device__ globals are zero-initialized at module load -> guards are
// permanently zero. Mid iterations therefore load float4 with NO bounds checks.
#define GY      8
#define GX      8
#define PROWS   2104
#define PITCH   2208
#define PLANE   (PROWS * PITCH)
#define BUFSZ   (C_IMG * PLANE)

__device__ float g_U[2][BUFSZ];

// ---------------- one side-window iteration (3 modes) ----------------
#define TH 30
#define TROWS (TH + 2*RAD)        // 40
#define TW 128
#define TCOLS 148                 // 37 float4; bank-friendly stride
#define TC4   (TCOLS/4)           // 37
#define NF4   (TROWS * TC4)       // 1480
#define H6W   138                 // 6 segments x 23 cols, fully covered

#define MODE_FIRST 0
#define MODE_MID   1
#define MODE_LAST  2

// Stage-3 vertical walk with lead sums.
// FULL=true: every row stores (only xok checked). Otherwise rows [lo,hi) store.
template<bool FULL>
__device__ __forceinline__ void walk(const float* __restrict__ hp,
                                     const float* __restrict__ hp5,
                                     const float* __restrict__ cp,
                                     float* __restrict__ ptr, int stride,
                                     int base, bool xok, int lo, int hi)
{
    const float i36 = 1.0f / 36.0f;
    const float i66 = 1.0f / 66.0f;

    float rHL[7], rHR[7], rCc[7];
    #pragma unroll
    for (int j = 0; j < 7; j++) {
        int row = base + j;
        rHL[j] = hp[row * H6W];
        rHR[j] = hp5[row * H6W];
        rCc[j] = cp[row * TCOLS];
    }

    float A  = rHL[0] + rHL[1] + rHL[2] + rHL[3] + rHL[4] + rHL[5];
    float B  = rHR[0] + rHR[1] + rHR[2] + rHR[3] + rHR[4] + rHR[5];
    float C6 = rCc[0] + rCc[1] + rCc[2] + rCc[3] + rCc[4] + rCc[5];
    float Dw = A + B - C6;

    float Ah[6], Bh[6], Dh[6];
    Ah[5] = A; Bh[5] = B; Dh[5] = Dw;

    // prologue j=6 (row already in ring)
    A  += rHL[6] - rHL[0];
    B  += rHR[6] - rHR[0];
    C6 += rCc[6] - rCc[0];
    Dw  = A + B - C6;
    Ah[0] = A; Bh[0] = B; Dh[0] = Dw;

    // prologue j=7..9
    #pragma unroll
    for (int j = 7; j <= 9; j++) {
        int row = base + j;
        float nHL = hp[row * H6W];
        float nHR = hp5[row * H6W];
        float nCc = cp[row * TCOLS];
        A  += nHL - rHL[(j - 6) % 7];
        B  += nHR - rHR[(j - 6) % 7];
        C6 += nCc - rCc[(j - 6) % 7];
        rHL[j % 7] = nHL; rHR[j % 7] = nHR; rCc[j % 7] = nCc;
        Dw = A + B - C6;
        Ah[j % 6] = A; Bh[j % 6] = B; Dh[j % 6] = Dw;
    }

    // main walk: ly = 0..TH/2-1, lead j = 10+ly
    #pragma unroll
    for (int ly = 0; ly < TH / 2; ly++) {
        const int j = 10 + ly;
        {
            int row = base + j;
            float nHL = hp[row * H6W];
            float nHR = hp5[row * H6W];
            float nCc = cp[row * TCOLS];
            A  += nHL - rHL[(j - 6) % 7];
            B  += nHR - rHR[(j - 6) % 7];
            C6 += nCc - rCc[(j - 6) % 7];
            rHL[j % 7] = nHL; rHR[j % 7] = nHR; rCc[j % 7] = nCc;
            Dw = A + B - C6;
        }

        const float uL = Ah[(j - 5) % 6];
        const float uR = Bh[(j - 5) % 6];
        const float uF = Dh[(j - 5) % 6];
        Ah[j % 6] = A; Bh[j % 6] = B; Dh[j % 6] = Dw;

        const float hL = rHL[(j - 5) % 7];
        const float hR = rHR[(j - 5) % 7];
        const float c0 = rCc[(j - 5) % 7];
        const float nc0 = -c0;

        const float fL = uL + A - hL;
        const float fR = uR + B - hR;

        // deltas, reference order [LL,LR,RL,RR,L*k,R*k,k*L,k*R]
        const float d0 = fmaf(uL, i36, nc0);
        const float d1 = fmaf(uR, i36, nc0);
        const float d2 = fmaf(A,  i36, nc0);
        const float d3 = fmaf(B,  i36, nc0);
        const float d4 = fmaf(uF, i66, nc0);
        const float d5 = fmaf(Dw, i66, nc0);
        const float d6 = fmaf(fL, i66, nc0);
        const float d7 = fmaf(fR, i66, nc0);

        // Tournament argmin, first-min-on-tie; |.| free on FSETP operands.
        const float w01 = (fabsf(d1) < fabsf(d0)) ? d1 : d0;
        const float w23 = (fabsf(d3) < fabsf(d2)) ? d3 : d2;
        const float w45 = (fabsf(d5) < fabsf(d4)) ? d5 : d4;
        const float w67 = (fabsf(d7) < fabsf(d6)) ? d7 : d6;
        const float w03 = (fabsf(w23) < fabsf(w01)) ? w23 : w01;
        const float w47 = (fabsf(w67) < fabsf(w45)) ? w67 : w45;
        const float bd  = (fabsf(w47) < fabsf(w03)) ? w47 : w03;

        if (FULL) {
            if (xok) ptr[ly * stride] = c0 + bd;
        } else {
            if (xok && ly >= lo && ly < hi) ptr[ly * stride] = c0 + bd;
        }
    }
}

template<int MODE>
__global__ __launch_bounds__(256)
void swf_iter(const float* __restrict__ img, float* __restrict__ out, int s) {
    float* __restrict__ Dst = (MODE == MODE_FIRST) ? g_U[0] : g_U[s ^ 1];

    __shared__ float tile[TROWS * TCOLS];   // 40*148 floats
    __shared__ float h6[TROWS * H6W];       // 40*138 floats

    const int c  = blockIdx.z;
    const int x0 = blockIdx.x * TW;
    const int y0 = blockIdx.y * TH;
    const int t  = threadIdx.x;             // 0..255
    float* __restrict__ Dp = Dst + c * PLANE;

    // ---- Stage 1 ----
    if (MODE == MODE_FIRST) {
        // Gather directly from HWC img with edge replicate; zero outside the
        // padded field. Scalar + clamped, paid only on iteration 0.
        for (int idx = t; idx < TROWS * TCOLS; idx += 256) {
            int r   = idx / TCOLS;
            int lxc = idx - r * TCOLS;
            int y = y0 + r - 5;             // padded-field row
            int x = x0 + lxc - 8;           // padded-field col
            float v = 0.0f;
            if (y >= 0 && y < PH && x >= 0 && x < PW) {
                int sy = y - RAD; sy = sy < 0 ? 0 : (sy > H_IMG - 1 ? H_IMG - 1 : sy);
                int sx = x - RAD; sx = sx < 0 ? 0 : (sx > W_IMG - 1 ? W_IMG - 1 : sx);
                v = img[(sy * W_IMG + sx) * C_IMG + c];
            }
            tile[idx] = v;
        }
    } else {
        // Unconditional float4 tile load (guards supply zeros).
        // Independent per-k address computation: all 6 LDGs issue back-to-back.
        const float* __restrict__ Sp = g_U[s] + c * PLANE;
        const float4* __restrict__ Sp4 =
            (const float4*)(Sp + (y0 + 3) * PITCH + x0);
        float4* tile4 = (float4*)tile;
        #pragma unroll
        for (int k = 0; k < 6; k++) {
            int idx = t + k * 256;
            if (idx < NF4) {
                int r  = idx / TC4;
                int c4 = idx - r * TC4;
                tile4[r * TC4 + c4] = Sp4[r * (PITCH / 4) + c4];
            }
        }
    }
    __syncthreads();

    // ---- Stage 2: horizontal extended 6-sums, fully unrolled, LDS ring ----
    if (t < TROWS * 6) {
        int r   = t / 6;
        int seg = t - r * 6;                 // 0..5
        int sx  = seg * 23;
        const float* trow = &tile[r * TCOLS + sx];
        float* hrow = &h6[r * H6W + sx];

        float e0 = trow[3], e1 = trow[4], e2 = trow[5],
              e3 = trow[6], e4 = trow[7], e5 = trow[8];
        float sum = e0 + e1 + e2 + e3 + e4 + e5;
        hrow[0] = sum;
        float e[6] = {e0, e1, e2, e3, e4, e5};
        #pragma unroll
        for (int i = 1; i < 23; i++) {
            float nl = trow[i + 8];
            sum += nl - e[(i - 1) % 6];
            e[(i - 1) % 6] = nl;
            hrow[i] = sum;
        }
    }
    __syncthreads();

    // ---- Stage 3 ----
    const int lx   = t & 127;
    const int half = t >> 7;
    const int base = half * (TH / 2);        // 0 or 15
    const int gx   = x0 + lx;

    const float* hp  = h6 + lx;
    const float* hp5 = h6 + lx + 5;
    const float* cp  = tile + lx + 8;

    const int row0 = y0 + base;              // first output row (padded field)

    if (MODE == MODE_LAST) {
        // Write cropped HWC output directly: valid gy,gx in [5, 2052].
        const bool xok = (gx >= RAD) && (gx < PW - RAD);
        int lo = RAD - row0;        if (lo < 0) lo = 0;
        int hi = (PH - RAD) - row0; if (hi > TH / 2) hi = TH / 2;
        float* optr = out + (((row0 - RAD) * W_IMG) + (gx - RAD)) * C_IMG + c;
        walk<false>(hp, hp5, cp, optr, W_IMG * C_IMG, base, xok, lo, hi);
    } else {
        const bool xok = (gx < PW);
        float* Drow = Dp + (row0 + GY) * PITCH + gx + GX;
        if (row0 + TH / 2 <= PH) {
            walk<true>(hp, hp5, cp, Drow, PITCH, base, xok, 0, TH / 2);
        } else {
            int nvalid = PH - row0;
            walk<false>(hp, hp5, cp, Drow, PITCH, base, xok, 0, nvalid);
        }
    }
}

extern "C" void kernel_launch(void* const* d_in, const int* in_sizes, int n_in,
                              void* d_out, int out_size) {
    const float* img = (const float*)d_in[0];   // (2048,2048,3) f32; d_in[1] hardcoded
    float* out = (float*)d_out;

    dim3 block(256, 1, 1);
    dim3 grid((PW + TW - 1) / TW, (PH + TH - 1) / TH, C_IMG);

    // iter 0: img -> g_U[0]
    swf_iter<MODE_FIRST><<<grid, block>>>(img, out, 0);
    // iters 1..8: g_U[(i-1)&1] -> g_U[i&1]
    for (int i = 1; i <= 8; i++) {
        swf_iter<MODE_MID><<<grid, block>>>(img, out, (i - 1) & 1);
    }
    // iter 9: g_U[0] -> out (cropped HWC)
    swf_iter<MODE_LAST><<<grid, block>>>(img, out, 0);
}

// round 15
// speedup vs baseline: 1.1952x; 1.0706x over previous
#include <cuda_runtime.h>
#include <cuda_bf16.h>

// ---------------- problem constants ----------------
#define H_IMG   2048
#define W_IMG   2048
#define C_IMG   3
#define RAD     5
#define NITER   10
#define PH      (H_IMG + 2*RAD)   // 2058
#define PW      (W_IMG + 2*RAD)   // 2058

// Guarded buffer layout: interior pixel (y,x) lives at row y+GY, col x+GX.
// Guard bands are NEVER written by any kernel (all stores are interior-only),
// and __device__ globals are zero-initialized at module load -> guards are
// permanently zero. Mid iterations therefore load float4 with NO bounds checks.
#define GY      8
#define GX      8
#define PROWS   2104
#define PITCH   2208
#define PLANE   (PROWS * PITCH)
#define BUFSZ   (C_IMG * PLANE)

__device__ float g_U[2][BUFSZ];

// ---------------- packed f32x2 helpers (sm_103a; PTX-only ops) ----------------
typedef unsigned long long u64v2;

#define PACK2(out, lo, hi) \
    asm("mov.b64 %0, {%1, %2};" : "=l"(out) : "f"(lo), "f"(hi))
#define UNPACK2(lo, hi, in) \
    asm("mov.b64 {%0, %1}, %2;" : "=f"(lo), "=f"(hi) : "l"(in))
#define ADD2(out, a, b) \
    asm("add.rn.f32x2 %0, %1, %2;" : "=l"(out) : "l"(a), "l"(b))
#define FMA2(out, a, b, c) \
    asm("fma.rn.f32x2 %0, %1, %2, %3;" : "=l"(out) : "l"(a), "l"(b), "l"(c))

// ---------------- one side-window iteration (3 modes) ----------------
#define TH 30
#define TROWS (TH + 2*RAD)        // 40
#define TW 128
#define TCOLS 148                 // 37 float4; bank-friendly stride
#define TC4   (TCOLS/4)           // 37
#define NF4   (TROWS * TC4)       // 1480
#define H6W   138                 // 6 segments x 23 cols, fully covered

#define MODE_FIRST 0
#define MODE_MID   1
#define MODE_LAST  2

// Stage-3 vertical walk with lead sums; (L,R) lanes packed as f32x2.
// FULL=true: every row stores (only xok checked). Otherwise rows [lo,hi) store.
template<bool FULL>
__device__ __forceinline__ void walk(const float* __restrict__ hp,
                                     const float* __restrict__ hp5,
                                     const float* __restrict__ cp,
                                     float* __restrict__ ptr, int stride,
                                     int base, bool xok, int lo, int hi)
{
    const float i36 = 1.0f / 36.0f;
    const float i66 = 1.0f / 66.0f;
    u64v2 I36x2, I66x2, NEG1x2;
    PACK2(I36x2, i36, i36);
    PACK2(I66x2, i66, i66);
    {
        const float m1 = -1.0f;
        PACK2(NEG1x2, m1, m1);
    }

    // ring: rH[j] = {HL,HR} packed; rCc scalar center column
    u64v2 rH[7];
    float rCc[7];
    #pragma unroll
    for (int j = 0; j < 7; j++) {
        int row = base + j;
        float nHL = hp[row * H6W];
        float nHR = hp5[row * H6W];
        u64v2 nH; PACK2(nH, nHL, nHR);
        rH[j] = nH;
        rCc[j] = cp[row * TCOLS];
    }

    // lead sums at j=5: AB = {A,B}
    u64v2 AB;
    {
        u64v2 t01, t23, t45;
        ADD2(t01, rH[0], rH[1]);
        ADD2(t23, rH[2], rH[3]);
        ADD2(t45, rH[4], rH[5]);
        ADD2(t01, t01, t23);
        ADD2(AB, t01, t45);
    }
    float C6 = rCc[0] + rCc[1] + rCc[2] + rCc[3] + rCc[4] + rCc[5];
    float a_, b_;
    UNPACK2(a_, b_, AB);
    float Dw = a_ + b_ - C6;

    u64v2 ABh[6];
    float Dh[6];
    ABh[5] = AB; Dh[5] = Dw;

    // prologue j=6 (row already in ring)
    {
        u64v2 d; FMA2(d, rH[0], NEG1x2, rH[6]);   // rH6 - rH0
        ADD2(AB, AB, d);
    }
    C6 += rCc[6] - rCc[0];
    UNPACK2(a_, b_, AB);
    Dw = a_ + b_ - C6;
    ABh[0] = AB; Dh[0] = Dw;

    // prologue j=7..9
    #pragma unroll
    for (int j = 7; j <= 9; j++) {
        int row = base + j;
        float nHL = hp[row * H6W];
        float nHR = hp5[row * H6W];
        float nCc = cp[row * TCOLS];
        u64v2 nH; PACK2(nH, nHL, nHR);
        u64v2 d; FMA2(d, rH[(j - 6) % 7], NEG1x2, nH);
        ADD2(AB, AB, d);
        C6 += nCc - rCc[(j - 6) % 7];
        rH[j % 7] = nH; rCc[j % 7] = nCc;
        UNPACK2(a_, b_, AB);
        Dw = a_ + b_ - C6;
        ABh[j % 6] = AB; Dh[j % 6] = Dw;
    }

    // main walk: ly = 0..TH/2-1, lead j = 10+ly
    #pragma unroll
    for (int ly = 0; ly < TH / 2; ly++) {
        const int j = 10 + ly;
        {
            int row = base + j;
            float nHL = hp[row * H6W];
            float nHR = hp5[row * H6W];
            float nCc = cp[row * TCOLS];
            u64v2 nH; PACK2(nH, nHL, nHR);
            u64v2 d; FMA2(d, rH[(j - 6) % 7], NEG1x2, nH);
            ADD2(AB, AB, d);
            C6 += nCc - rCc[(j - 6) % 7];
            rH[j % 7] = nH; rCc[j % 7] = nCc;
            UNPACK2(a_, b_, AB);
            Dw = a_ + b_ - C6;
        }

        const u64v2 uAB = ABh[(j - 5) % 6];      // {uL,uR}
        const float uF  = Dh[(j - 5) % 6];
        ABh[j % 6] = AB; Dh[j % 6] = Dw;

        const u64v2 hH = rH[(j - 5) % 7];        // {hL,hR}
        const float c0 = rCc[(j - 5) % 7];
        const float nc0 = -c0;
        u64v2 nc0x2; PACK2(nc0x2, nc0, nc0);

        u64v2 sAB; ADD2(sAB, uAB, AB);           // {uL+A, uR+B}
        u64v2 fLR; FMA2(fLR, hH, NEG1x2, sAB);   // {fL, fR}

        // deltas, reference order [LL,LR,RL,RR,L*k,R*k,k*L,k*R]
        u64v2 d01, d23, d67;
        FMA2(d01, uAB, I36x2, nc0x2);            // d0,d1
        FMA2(d23, AB,  I36x2, nc0x2);            // d2,d3
        FMA2(d67, fLR, I66x2, nc0x2);            // d6,d7
        const float d4 = fmaf(uF, i66, nc0);
        const float d5 = fmaf(Dw, i66, nc0);

        float d0, d1, d2, d3, d6, d7;
        UNPACK2(d0, d1, d01);
        UNPACK2(d2, d3, d23);
        UNPACK2(d6, d7, d67);

        // Tournament argmin, first-min-on-tie; |.| free on FSETP operands.
        const float w01 = (fabsf(d1) < fabsf(d0)) ? d1 : d0;
        const float w23 = (fabsf(d3) < fabsf(d2)) ? d3 : d2;
        const float w45 = (fabsf(d5) < fabsf(d4)) ? d5 : d4;
        const float w67 = (fabsf(d7) < fabsf(d6)) ? d7 : d6;
        const float w03 = (fabsf(w23) < fabsf(w01)) ? w23 : w01;
        const float w47 = (fabsf(w67) < fabsf(w45)) ? w67 : w45;
        const float bd  = (fabsf(w47) < fabsf(w03)) ? w47 : w03;

        if (FULL) {
            if (xok) ptr[ly * stride] = c0 + bd;
        } else {
            if (xok && ly >= lo && ly < hi) ptr[ly * stride] = c0 + bd;
        }
    }
}

template<int MODE>
__global__ __launch_bounds__(256)
void swf_iter(const float* __restrict__ img, float* __restrict__ out, int s) {
    float* __restrict__ Dst = (MODE == MODE_FIRST) ? g_U[0] : g_U[s ^ 1];

    __shared__ float tile[TROWS * TCOLS];   // 40*148 floats
    __shared__ float h6[TROWS * H6W];       // 40*138 floats

    const int c  = blockIdx.z;
    const int x0 = blockIdx.x * TW;
    const int y0 = blockIdx.y * TH;
    const int t  = threadIdx.x;             // 0..255
    float* __restrict__ Dp = Dst + c * PLANE;

    // ---- Stage 1 ----
    if (MODE == MODE_FIRST) {
        // Gather directly from HWC img with edge replicate; zero outside the
        // padded field. Scalar + clamped, paid only on iteration 0.
        for (int idx = t; idx < TROWS * TCOLS; idx += 256) {
            int r   = idx / TCOLS;
            int lxc = idx - r * TCOLS;
            int y = y0 + r - 5;             // padded-field row
            int x = x0 + lxc - 8;           // padded-field col
            float v = 0.0f;
            if (y >= 0 && y < PH && x >= 0 && x < PW) {
                int sy = y - RAD; sy = sy < 0 ? 0 : (sy > H_IMG - 1 ? H_IMG - 1 : sy);
                int sx = x - RAD; sx = sx < 0 ? 0 : (sx > W_IMG - 1 ? W_IMG - 1 : sx);
                v = img[(sy * W_IMG + sx) * C_IMG + c];
            }
            tile[idx] = v;
        }
    } else {
        // Unconditional float4 tile load (guards supply zeros).
        // Independent per-k address computation: all 6 LDGs issue back-to-back.
        const float* __restrict__ Sp = g_U[s] + c * PLANE;
        const float4* __restrict__ Sp4 =
            (const float4*)(Sp + (y0 + 3) * PITCH + x0);
        float4* tile4 = (float4*)tile;
        #pragma unroll
        for (int k = 0; k < 6; k++) {
            int idx = t + k * 256;
            if (idx < NF4) {
                int r  = idx / TC4;
                int c4 = idx - r * TC4;
                tile4[r * TC4 + c4] = Sp4[r * (PITCH / 4) + c4];
            }
        }
    }
    __syncthreads();

    // ---- Stage 2: horizontal extended 6-sums, fully unrolled, LDS ring ----
    if (t < TROWS * 6) {
        int r   = t / 6;
        int seg = t - r * 6;                 // 0..5
        int sx  = seg * 23;
        const float* trow = &tile[r * TCOLS + sx];
        float* hrow = &h6[r * H6W + sx];

        float e0 = trow[3], e1 = trow[4], e2 = trow[5],
              e3 = trow[6], e4 = trow[7], e5 = trow[8];
        float sum = e0 + e1 + e2 + e3 + e4 + e5;
        hrow[0] = sum;
        float e[6] = {e0, e1, e2, e3, e4, e5};
        #pragma unroll
        for (int i = 1; i < 23; i++) {
            float nl = trow[i + 8];
            sum += nl - e[(i - 1) % 6];
            e[(i - 1) % 6] = nl;
            hrow[i] = sum;
        }
    }
    __syncthreads();

    // ---- Stage 3 ----
    const int lx   = t & 127;
    const int half = t >> 7;
    const int base = half * (TH / 2);        // 0 or 15
    const int gx   = x0 + lx;

    const float* hp  = h6 + lx;
    const float* hp5 = h6 + lx + 5;
    const float* cp  = tile + lx + 8;

    const int row0 = y0 + base;              // first output row (padded field)

    if (MODE == MODE_LAST) {
        // Write cropped HWC output directly: valid gy,gx in [5, 2052].
        const bool xok = (gx >= RAD) && (gx < PW - RAD);
        int lo = RAD - row0;        if (lo < 0) lo = 0;
        int hi = (PH - RAD) - row0; if (hi > TH / 2) hi = TH / 2;
        float* optr = out + (((row0 - RAD) * W_IMG) + (gx - RAD)) * C_IMG + c;
        walk<false>(hp, hp5, cp, optr, W_IMG * C_IMG, base, xok, lo, hi);
    } else {
        const bool xok = (gx < PW);
        float* Drow = Dp + (row0 + GY) * PITCH + gx + GX;
        if (row0 + TH / 2 <= PH) {
            walk<true>(hp, hp5, cp, Drow, PITCH, base, xok, 0, TH / 2);
        } else {
            int nvalid = PH - row0;
            walk<false>(hp, hp5, cp, Drow, PITCH, base, xok, 0, nvalid);
        }
    }
}

extern "C" void kernel_launch(void* const* d_in, const int* in_sizes, int n_in,
                              void* d_out, int out_size) {
    const float* img = (const float*)d_in[0];   // (2048,2048,3) f32; d_in[1] hardcoded
    float* out = (float*)d_out;

    dim3 block(256, 1, 1);
    dim3 grid((PW + TW - 1) / TW, (PH + TH - 1) / TH, C_IMG);

    // iter 0: img -> g_U[0]
    swf_iter<MODE_FIRST><<<grid, block>>>(img, out, 0);
    // iters 1..8: g_U[(i-1)&1] -> g_U[i&1]
    for (int i = 1; i <= 8; i++) {
        swf_iter<MODE_MID><<<grid, block>>>(img, out, (i - 1) & 1);
    }
    // iter 9: g_U[0] -> out (cropped HWC)
    swf_iter<MODE_LAST><<<grid, block>>>(img, out, 0);
}